// round 2
// baseline (speedup 1.0000x reference)
#include <cuda_runtime.h>
#include <cstdint>

#define BATCH 32
#define TT    512
#define NGATE 1024   // 4*H
#define HDIM  256
#define OUTW  512

// Scratch (static device globals — no allocation allowed)
__device__ float g_xg[(size_t)2 * BATCH * TT * NGATE];   // 128 MB: pre-activations, reused per layer
__device__ float g_h1[(size_t)BATCH * TT * OUTW];        // 32 MB: layer-0 output (fwd||bwd concat)

// ---------------------------------------------------------------------------
// Input projection: xg[dir][b][t][j] = src[b][t][:] . W[dir][j][:] + bias[dir][j]
// M = 16384 rows (b*t), N = 1024, K = 256 or 512. BM=BN=64, BK=16, 256 thr, 4x4 microtile.
// ---------------------------------------------------------------------------
__global__ __launch_bounds__(256) void gemm_proj(
    const float* __restrict__ src, int K,
    const float* __restrict__ Wf, const float* __restrict__ bf,
    const float* __restrict__ Wb, const float* __restrict__ bb)
{
    const int dir = blockIdx.z;
    const float* __restrict__ W    = dir ? Wb : Wf;
    const float* __restrict__ bias = dir ? bb : bf;
    const int j0 = blockIdx.x * 64;
    const int r0 = blockIdx.y * 64;

    __shared__ __align__(16) float As[16][72];
    __shared__ __align__(16) float Bs[16][72];

    const int tid = threadIdx.x;
    const int lr  = tid >> 2;          // 0..63 : row within tile for loads
    const int lc  = (tid & 3) << 2;    // 0,4,8,12 : k offset for loads
    const int tn  = (tid & 15) << 2;   // 0..60 : micro col
    const int tm  = (tid >> 4) << 2;   // 0..60 : micro row

    float acc[4][4];
    #pragma unroll
    for (int i = 0; i < 4; i++)
        #pragma unroll
        for (int u = 0; u < 4; u++) acc[i][u] = 0.f;

    const float* aptr = src + (size_t)(r0 + lr) * K + lc;
    const float* bptr = W   + (size_t)(j0 + lr) * K + lc;

    for (int k0 = 0; k0 < K; k0 += 16) {
        float4 av = *(const float4*)(aptr + k0);
        float4 bv = *(const float4*)(bptr + k0);
        __syncthreads();
        As[lc + 0][lr] = av.x; As[lc + 1][lr] = av.y;
        As[lc + 2][lr] = av.z; As[lc + 3][lr] = av.w;
        Bs[lc + 0][lr] = bv.x; Bs[lc + 1][lr] = bv.y;
        Bs[lc + 2][lr] = bv.z; Bs[lc + 3][lr] = bv.w;
        __syncthreads();
        #pragma unroll
        for (int kk = 0; kk < 16; ++kk) {
            float4 a4 = *(const float4*)&As[kk][tm];
            float4 b4 = *(const float4*)&Bs[kk][tn];
            acc[0][0] += a4.x * b4.x; acc[0][1] += a4.x * b4.y;
            acc[0][2] += a4.x * b4.z; acc[0][3] += a4.x * b4.w;
            acc[1][0] += a4.y * b4.x; acc[1][1] += a4.y * b4.y;
            acc[1][2] += a4.y * b4.z; acc[1][3] += a4.y * b4.w;
            acc[2][0] += a4.z * b4.x; acc[2][1] += a4.z * b4.y;
            acc[2][2] += a4.z * b4.z; acc[2][3] += a4.z * b4.w;
            acc[3][0] += a4.w * b4.x; acc[3][1] += a4.w * b4.y;
            acc[3][2] += a4.w * b4.z; acc[3][3] += a4.w * b4.w;
        }
    }

    float4 bv4 = *(const float4*)&bias[j0 + tn];
    #pragma unroll
    for (int i = 0; i < 4; i++) {
        float4 o;
        o.x = acc[i][0] + bv4.x;
        o.y = acc[i][1] + bv4.y;
        o.z = acc[i][2] + bv4.z;
        o.w = acc[i][3] + bv4.w;
        *(float4*)(g_xg + ((size_t)dir * (BATCH * TT) + r0 + tm + i) * NGATE + j0 + tn) = o;
    }
}

// ---------------------------------------------------------------------------
// Recurrence: persistent cluster kernel.
// Grid: 128 CTAs = 2 dirs x 8 batch-groups(4 batches) x 8-CTA cluster.
// CTA rank n owns hidden units [32n, 32n+32) : gate rows {g*256 + 32n + r}.
// W_hh slice (128 rows x 256) lives in SMEM as [k/4][j][k%4] fp32 (128 KB).
// h (4 batches x 256) double-buffered in SMEM; per-step DSMEM push + 1 cluster barrier.
// ---------------------------------------------------------------------------
__device__ __forceinline__ float sigmoidf_(float x) { return 1.0f / (1.0f + __expf(-x)); }

__global__ __launch_bounds__(128, 1) __cluster_dims__(8, 1, 1)
void lstm_rec(const float* __restrict__ whhF, const float* __restrict__ whhB,
              float* __restrict__ out)
{
    extern __shared__ __align__(16) float smem[];
    float* Ws  = smem;                  // 32768 floats : [64][128][4]
    float* h_s = smem + 32768;          // 2048 floats  : [2][4][256]
    float* g_s = smem + 32768 + 2048;   // 512 floats   : [4][128]

    const int tid   = threadIdx.x;        // 128 threads
    const int brank = blockIdx.x & 7;     // rank in cluster
    const int cid   = blockIdx.x >> 3;    // 0..15
    const int dir   = cid >> 3;           // 0 fwd, 1 bwd
    const int bg    = cid & 7;            // batch group (4 batches)
    const float* __restrict__ whh = dir ? whhB : whhF;

    // Load W_hh slice into SMEM, packed float4 along k
    for (int idx = tid; idx < 128 * 256; idx += 128) {
        int j = idx >> 8;          // 0..127
        int k = idx & 255;
        int grow = ((j >> 5) << 8) + (brank << 5) + (j & 31);   // gate*256 + 32*rank + r
        Ws[((k >> 2) << 9) + (j << 2) + (k & 3)] = whh[(size_t)grow * HDIM + k];
    }
    for (int idx = tid; idx < 1024; idx += 128) h_s[idx] = 0.f;   // zero buffer 0
    __syncthreads();
    asm volatile("barrier.cluster.arrive.aligned;\n\tbarrier.cluster.wait.aligned;" ::: "memory");

    const int j        = tid;
    const int gate     = j >> 5;
    const int kl       = j & 31;
    const int j_global = (gate << 8) + (brank << 5) + kl;
    const int bb       = tid >> 5;   // epilogue batch index 0..3

    const float* xgb = g_xg + (((size_t)dir * BATCH + bg * 4) * TT) * NGATE;

    float c_state = 0.f;

    // u32 shared address of our h slot (buffer 0)
    uint32_t haddr0;
    {
        const float* p = h_s + bb * 256 + (brank << 5) + kl;
        asm volatile("{ .reg .u64 t; cvta.to.shared.u64 t, %1; cvt.u32.u64 %0, t; }"
                     : "=r"(haddr0) : "l"(p));
    }

    int t = dir ? (TT - 1) : 0;
    const int tstep = dir ? -1 : 1;

    float x0 = xgb[((size_t)0 * TT + t) * NGATE + j_global];
    float x1 = xgb[((size_t)1 * TT + t) * NGATE + j_global];
    float x2 = xgb[((size_t)2 * TT + t) * NGATE + j_global];
    float x3 = xgb[((size_t)3 * TT + t) * NGATE + j_global];

    int buf = 0;
    for (int it = 0; it < TT; ++it) {
        float acc0 = x0, acc1 = x1, acc2 = x2, acc3 = x3;
        const int tcur = t;

        // prefetch next step's xg (hidden behind the matvec)
        if (it + 1 < TT) {
            const int tnx = t + tstep;
            x0 = xgb[((size_t)0 * TT + tnx) * NGATE + j_global];
            x1 = xgb[((size_t)1 * TT + tnx) * NGATE + j_global];
            x2 = xgb[((size_t)2 * TT + tnx) * NGATE + j_global];
            x3 = xgb[((size_t)3 * TT + tnx) * NGATE + j_global];
        }

        const float4* W4  = (const float4*)Ws;
        const float4* h0p = (const float4*)(h_s + buf * 1024);
        const float4* h1p = h0p + 64;
        const float4* h2p = h0p + 128;
        const float4* h3p = h0p + 192;

        #pragma unroll 4
        for (int kk = 0; kk < 64; ++kk) {
            float4 w = W4[(kk << 7) + j];
            float4 a = h0p[kk];
            float4 b = h1p[kk];
            float4 c = h2p[kk];
            float4 d = h3p[kk];
            acc0 += w.x * a.x + w.y * a.y + w.z * a.z + w.w * a.w;
            acc1 += w.x * b.x + w.y * b.y + w.z * b.z + w.w * b.w;
            acc2 += w.x * c.x + w.y * c.y + w.z * c.z + w.w * c.w;
            acc3 += w.x * d.x + w.y * d.y + w.z * d.z + w.w * d.w;
        }

        g_s[      j] = acc0;
        g_s[128 + j] = acc1;
        g_s[256 + j] = acc2;
        g_s[384 + j] = acc3;
        __syncthreads();

        // epilogue: thread handles (batch bb, hidden kl)
        float gi = g_s[bb * 128 +      kl];
        float gf = g_s[bb * 128 + 32 + kl];
        float gg = g_s[bb * 128 + 64 + kl];
        float go = g_s[bb * 128 + 96 + kl];
        float i_ = sigmoidf_(gi);
        float f_ = sigmoidf_(gf);
        float g_ = tanhf(gg);
        float o_ = sigmoidf_(go);
        c_state = f_ * c_state + i_ * g_;
        float hval = o_ * tanhf(c_state);

        out[(((size_t)(bg * 4 + bb)) * TT + tcur) * OUTW + (dir << 8) + (brank << 5) + kl] = hval;

        // push h to all 8 CTAs' other buffer (DSMEM)
        uint32_t laddr = haddr0 + (uint32_t)((buf ^ 1) * 1024 * 4);
        #pragma unroll
        for (int rk = 0; rk < 8; ++rk) {
            uint32_t raddr;
            asm volatile("mapa.shared::cluster.u32 %0, %1, %2;" : "=r"(raddr) : "r"(laddr), "r"(rk));
            asm volatile("st.shared::cluster.f32 [%0], %1;" :: "r"(raddr), "f"(hval) : "memory");
        }

        // one cluster barrier per step: release pushes / acquire peers' pushes
        asm volatile("barrier.cluster.arrive.aligned;\n\tbarrier.cluster.wait.aligned;" ::: "memory");
        buf ^= 1;
        t += tstep;
    }
}

// ---------------------------------------------------------------------------
extern "C" void kernel_launch(void* const* d_in, const int* in_sizes, int n_in,
                              void* d_out, int out_size)
{
    const float* x         = (const float*)d_in[0];
    const float* w_ih_l0f  = (const float*)d_in[1];
    const float* w_hh_l0f  = (const float*)d_in[2];
    const float* b_l0f     = (const float*)d_in[3];
    const float* w_ih_l0b  = (const float*)d_in[4];
    const float* w_hh_l0b  = (const float*)d_in[5];
    const float* b_l0b     = (const float*)d_in[6];
    const float* w_ih_l1f  = (const float*)d_in[7];
    const float* w_hh_l1f  = (const float*)d_in[8];
    const float* b_l1f     = (const float*)d_in[9];
    const float* w_ih_l1b  = (const float*)d_in[10];
    const float* w_hh_l1b  = (const float*)d_in[11];
    const float* b_l1b     = (const float*)d_in[12];
    float* out = (float*)d_out;

    float* h1 = nullptr;
    cudaGetSymbolAddress((void**)&h1, g_h1);

    const int smemRec = (32768 + 2048 + 512) * 4;   // 141312 B
    cudaFuncSetAttribute(lstm_rec, cudaFuncAttributeMaxDynamicSharedMemorySize, smemRec);

    dim3 ggrid(16, 256, 2);   // N/64, M/64, dirs

    // Layer 0
    gemm_proj<<<ggrid, 256>>>(x, 256, w_ih_l0f, b_l0f, w_ih_l0b, b_l0b);
    lstm_rec<<<128, 128, smemRec>>>(w_hh_l0f, w_hh_l0b, h1);

    // Layer 1
    gemm_proj<<<ggrid, 256>>>(h1, 512, w_ih_l1f, b_l1f, w_ih_l1b, b_l1b);
    lstm_rec<<<128, 128, smemRec>>>(w_hh_l1f, w_hh_l1b, out);
}

// round 4
// speedup vs baseline: 1.1164x; 1.1164x over previous
#include <cuda_runtime.h>
#include <cstdint>
#include <cstring>

#define BATCH 32
#define TT    512
#define NGATE 1024   // 4*H
#define HDIM  256
#define OUTW  512

// Scratch (static device globals — no allocation allowed)
__device__ float g_xg[(size_t)2 * BATCH * TT * NGATE];   // pre-activations (both dirs)
__device__ float g_h1[(size_t)BATCH * TT * OUTW];        // layer-0 output (fwd||bwd concat)

// ---------------- f32x2 helpers ----------------
__device__ __forceinline__ void ffma2(unsigned long long& d, unsigned long long a, unsigned long long b) {
    asm("fma.rn.f32x2 %0, %1, %2, %0;" : "+l"(d) : "l"(a), "l"(b));
}
__device__ __forceinline__ float fold2(unsigned long long v) {
    float2 f; memcpy(&f, &v, 8); return f.x + f.y;
}
__device__ __forceinline__ unsigned long long pack2(float lo, float hi) {
    unsigned long long u;
    asm("mov.b64 %0, {%1, %2};" : "=l"(u) : "f"(lo), "f"(hi));
    return u;
}

// ---------------------------------------------------------------------------
// Input projection GEMM: xg[dir][r][j] = src[r][:] . W[dir][j][:] + bias[j]
// M=16384, N=1024, K=256/512. 64x64 tile, 4x4 microtile, k-paired f32x2 accum.
// ---------------------------------------------------------------------------
__global__ __launch_bounds__(256) void gemm_proj(
    const float* __restrict__ src, int K,
    const float* __restrict__ Wf, const float* __restrict__ bf,
    const float* __restrict__ Wb, const float* __restrict__ bb)
{
    const int dir = blockIdx.z;
    const float* __restrict__ W    = dir ? Wb : Wf;
    const float* __restrict__ bias = dir ? bb : bf;
    const int j0 = blockIdx.x * 64;
    const int r0 = blockIdx.y * 64;

    __shared__ __align__(16) float2 As2[8][64];
    __shared__ __align__(16) float2 Bs2[8][64];

    const int tid = threadIdx.x;
    const int lr  = tid >> 2;          // 0..63
    const int lc  = (tid & 3) << 2;    // 0,4,8,12
    const int tn  = (tid & 15) << 2;   // 0..60
    const int tm  = (tid >> 4) << 2;   // 0..60
    const int kp0 = lc >> 1;           // 0,2,4,6

    unsigned long long acc[4][4];
    #pragma unroll
    for (int i = 0; i < 4; i++)
        #pragma unroll
        for (int u = 0; u < 4; u++) acc[i][u] = 0ull;

    const float* aptr = src + (size_t)(r0 + lr) * K + lc;
    const float* bptr = W   + (size_t)(j0 + lr) * K + lc;

    for (int k0 = 0; k0 < K; k0 += 16) {
        float4 av = *(const float4*)(aptr + k0);
        float4 bv = *(const float4*)(bptr + k0);
        __syncthreads();
        As2[kp0    ][lr] = make_float2(av.x, av.y);
        As2[kp0 + 1][lr] = make_float2(av.z, av.w);
        Bs2[kp0    ][lr] = make_float2(bv.x, bv.y);
        Bs2[kp0 + 1][lr] = make_float2(bv.z, bv.w);
        __syncthreads();
        #pragma unroll
        for (int kp = 0; kp < 8; ++kp) {
            ulonglong2 a0 = *reinterpret_cast<const ulonglong2*>(&As2[kp][tm]);
            ulonglong2 a1 = *reinterpret_cast<const ulonglong2*>(&As2[kp][tm + 2]);
            ulonglong2 b0 = *reinterpret_cast<const ulonglong2*>(&Bs2[kp][tn]);
            ulonglong2 b1 = *reinterpret_cast<const ulonglong2*>(&Bs2[kp][tn + 2]);
            ffma2(acc[0][0], a0.x, b0.x); ffma2(acc[0][1], a0.x, b0.y);
            ffma2(acc[0][2], a0.x, b1.x); ffma2(acc[0][3], a0.x, b1.y);
            ffma2(acc[1][0], a0.y, b0.x); ffma2(acc[1][1], a0.y, b0.y);
            ffma2(acc[1][2], a0.y, b1.x); ffma2(acc[1][3], a0.y, b1.y);
            ffma2(acc[2][0], a1.x, b0.x); ffma2(acc[2][1], a1.x, b0.y);
            ffma2(acc[2][2], a1.x, b1.x); ffma2(acc[2][3], a1.x, b1.y);
            ffma2(acc[3][0], a1.y, b0.x); ffma2(acc[3][1], a1.y, b0.y);
            ffma2(acc[3][2], a1.y, b1.x); ffma2(acc[3][3], a1.y, b1.y);
        }
    }

    float4 bv4 = *(const float4*)&bias[j0 + tn];
    #pragma unroll
    for (int i = 0; i < 4; i++) {
        float4 o;
        o.x = fold2(acc[i][0]) + bv4.x;
        o.y = fold2(acc[i][1]) + bv4.y;
        o.z = fold2(acc[i][2]) + bv4.z;
        o.w = fold2(acc[i][3]) + bv4.w;
        *(float4*)(g_xg + ((size_t)dir * (BATCH * TT) + r0 + tm + i) * NGATE + j0 + tn) = o;
    }
}

// ---------------------------------------------------------------------------
// Recurrence v2: W_hh in REGISTERS, f32x2 math, vectorized DSMEM h exchange.
// Grid: 128 CTAs = 2 dirs x 8 batch-groups(4 batches) x 8-CTA cluster.
// CTA rank owns 128 gate rows; 256 threads = 128 gates x 2 k-halves.
// Each thread holds 128 W floats (64 f32x2) in registers.
// ---------------------------------------------------------------------------
__device__ __forceinline__ float sigmoidf_(float x) { return 1.0f / (1.0f + __expf(-x)); }

__global__ __launch_bounds__(256, 1) __cluster_dims__(8, 1, 1)
void lstm_rec(const float* __restrict__ whhF, const float* __restrict__ whhB,
              float* __restrict__ out)
{
    __shared__ __align__(16) float h_s[2 * 1024];   // [2 buf][4 batch][256]
    __shared__ float g_s [512];                     // kh=0 partials (+x)
    __shared__ float rsum[512];                     // kh=1 partials
    __shared__ __align__(16) float hstage[128];

    const int tid   = threadIdx.x;
    const int j     = tid & 127;          // gate within CTA slice
    const int kh    = tid >> 7;           // k-half
    const int brank = blockIdx.x & 7;
    const int cid   = blockIdx.x >> 3;
    const int dir   = cid >> 3;
    const int bg    = cid & 7;
    const float* __restrict__ whh = dir ? whhB : whhF;

    const int gate = j >> 5;
    const int kl   = j & 31;
    const int grow = (gate << 8) + (brank << 5) + kl;   // global gate row

    // ---- W_hh slice into registers: 128 floats = 64 f32x2 ----
    unsigned long long Wreg[64];
    {
        const float* wrow = whh + (size_t)grow * HDIM + (kh << 7);
        #pragma unroll
        for (int q = 0; q < 64; ++q) {
            float2 w = *(const float2*)(wrow + 2 * q);
            memcpy(&Wreg[q], &w, 8);
        }
    }

    // zero both h buffers
    for (int idx = tid; idx < 2048; idx += 256) h_s[idx] = 0.f;
    __syncthreads();
    asm volatile("barrier.cluster.arrive.aligned;\n\tbarrier.cluster.wait.aligned;" ::: "memory");

    // precomputed DSMEM push target: this thread pushes one float4 to peer rk
    uint32_t mypeer;
    {
        uint32_t hbase;
        asm volatile("{ .reg .u64 t; cvta.to.shared.u64 t, %1; cvt.u32.u64 %0, t; }"
                     : "=r"(hbase) : "l"((const float*)h_s));
        uint32_t rk = (uint32_t)(tid >> 5);   // 0..7
        asm volatile("mapa.shared::cluster.u32 %0, %1, %2;" : "=r"(mypeer) : "r"(hbase), "r"(rk));
    }
    const int i5 = tid & 31;
    const uint32_t push_off = ((uint32_t)(i5 >> 3) << 10) + ((uint32_t)brank << 7) + ((uint32_t)(i5 & 7) << 4);

    const float* xgb = g_xg + (((size_t)dir * BATCH + bg * 4) * TT) * NGATE;

    float c_state = 0.f;
    int t = dir ? (TT - 1) : 0;
    const int tstep = dir ? -1 : 1;

    float x0 = 0.f, x1 = 0.f, x2 = 0.f, x3 = 0.f;
    if (kh == 0) {
        x0 = xgb[((size_t)0 * TT + t) * NGATE + grow];
        x1 = xgb[((size_t)1 * TT + t) * NGATE + grow];
        x2 = xgb[((size_t)2 * TT + t) * NGATE + grow];
        x3 = xgb[((size_t)3 * TT + t) * NGATE + grow];
    }

    int buf = 0;
    for (int it = 0; it < TT; ++it) {
        unsigned long long acc0, acc1, acc2, acc3;
        if (kh == 0) {
            acc0 = pack2(x0, 0.f); acc1 = pack2(x1, 0.f);
            acc2 = pack2(x2, 0.f); acc3 = pack2(x3, 0.f);
        } else {
            acc0 = acc1 = acc2 = acc3 = 0ull;
        }

        // matvec over this thread's 128-k half, 4 batches
        // h_s batch stride = 256 floats = 64 ulonglong2  (R3 bug was +16/+32/+48)
        const ulonglong2* hptr = reinterpret_cast<const ulonglong2*>(h_s + (buf << 10) + (kh << 7));
        #pragma unroll
        for (int q = 0; q < 32; ++q) {
            ulonglong2 ha = hptr[q];
            ulonglong2 hb = hptr[q + 64];
            ulonglong2 hc = hptr[q + 128];
            ulonglong2 hd = hptr[q + 192];
            unsigned long long w0 = Wreg[2 * q], w1 = Wreg[2 * q + 1];
            ffma2(acc0, w0, ha.x); ffma2(acc1, w0, hb.x);
            ffma2(acc2, w0, hc.x); ffma2(acc3, w0, hd.x);
            ffma2(acc0, w1, ha.y); ffma2(acc1, w1, hb.y);
            ffma2(acc2, w1, hc.y); ffma2(acc3, w1, hd.y);
        }

        float s0 = fold2(acc0), s1 = fold2(acc1), s2 = fold2(acc2), s3 = fold2(acc3);
        if (kh == 0) {
            g_s[      j] = s0; g_s[128 + j] = s1; g_s[256 + j] = s2; g_s[384 + j] = s3;
        } else {
            rsum[      j] = s0; rsum[128 + j] = s1; rsum[256 + j] = s2; rsum[384 + j] = s3;
        }
        __syncthreads();

        float hval = 0.f;
        if (tid < 128) {
            const int bb   = tid >> 5;
            const int kloc = tid & 31;
            const int base = bb * 128 + kloc;
            float gi = g_s[base     ] + rsum[base     ];
            float gf = g_s[base + 32] + rsum[base + 32];
            float gg = g_s[base + 64] + rsum[base + 64];
            float go = g_s[base + 96] + rsum[base + 96];
            float i_ = sigmoidf_(gi);
            float f_ = sigmoidf_(gf);
            float g_ = tanhf(gg);
            float o_ = sigmoidf_(go);
            c_state = f_ * c_state + i_ * g_;
            hval = o_ * tanhf(c_state);
            hstage[tid] = hval;
        }
        __syncthreads();

        // vectorized DSMEM push: each thread sends one float4 to its peer
        {
            const float4 v = *(const float4*)&hstage[i5 << 2];
            uint32_t addr = mypeer + ((uint32_t)(buf ^ 1) << 12) + push_off;
            asm volatile("st.shared::cluster.v4.f32 [%0], {%1, %2, %3, %4};"
                         :: "r"(addr), "f"(v.x), "f"(v.y), "f"(v.z), "f"(v.w) : "memory");
        }
        asm volatile("barrier.cluster.arrive.aligned;" ::: "memory");

        // overlap with barrier: output store + next-x prefetch
        if (tid < 128) {
            const int bb   = tid >> 5;
            const int kloc = tid & 31;
            out[(((size_t)(bg * 4 + bb)) * TT + t) * OUTW + (dir << 8) + (brank << 5) + kloc] = hval;
        }
        if (kh == 0 && it + 1 < TT) {
            const int tnx = t + tstep;
            x0 = xgb[((size_t)0 * TT + tnx) * NGATE + grow];
            x1 = xgb[((size_t)1 * TT + tnx) * NGATE + grow];
            x2 = xgb[((size_t)2 * TT + tnx) * NGATE + grow];
            x3 = xgb[((size_t)3 * TT + tnx) * NGATE + grow];
        }

        asm volatile("barrier.cluster.wait.aligned;" ::: "memory");
        buf ^= 1;
        t += tstep;
    }
}

// ---------------------------------------------------------------------------
extern "C" void kernel_launch(void* const* d_in, const int* in_sizes, int n_in,
                              void* d_out, int out_size)
{
    const float* x         = (const float*)d_in[0];
    const float* w_ih_l0f  = (const float*)d_in[1];
    const float* w_hh_l0f  = (const float*)d_in[2];
    const float* b_l0f     = (const float*)d_in[3];
    const float* w_ih_l0b  = (const float*)d_in[4];
    const float* w_hh_l0b  = (const float*)d_in[5];
    const float* b_l0b     = (const float*)d_in[6];
    const float* w_ih_l1f  = (const float*)d_in[7];
    const float* w_hh_l1f  = (const float*)d_in[8];
    const float* b_l1f     = (const float*)d_in[9];
    const float* w_ih_l1b  = (const float*)d_in[10];
    const float* w_hh_l1b  = (const float*)d_in[11];
    const float* b_l1b     = (const float*)d_in[12];
    float* out = (float*)d_out;

    float* h1 = nullptr;
    cudaGetSymbolAddress((void**)&h1, g_h1);

    dim3 ggrid(16, 256, 2);   // N/64, M/64, dirs

    // Layer 0
    gemm_proj<<<ggrid, 256>>>(x, 256, w_ih_l0f, b_l0f, w_ih_l0b, b_l0b);
    lstm_rec<<<128, 256>>>(w_hh_l0f, w_hh_l0b, h1);

    // Layer 1
    gemm_proj<<<ggrid, 256>>>(h1, 512, w_ih_l1f, b_l1f, w_ih_l1b, b_l1b);
    lstm_rec<<<128, 256>>>(w_hh_l1f, w_hh_l1b, out);
}

// round 5
// speedup vs baseline: 1.1429x; 1.0237x over previous
#include <cuda_runtime.h>
#include <cstdint>
#include <cstring>

#define BATCH 32
#define TT    512
#define NGATE 1024   // 4*H
#define HDIM  256
#define OUTW  512

// Scratch (static device globals — no allocation allowed)
__device__ float g_xg[(size_t)2 * BATCH * TT * NGATE];   // pre-activations (both dirs)
__device__ float g_h1[(size_t)BATCH * TT * OUTW];        // layer-0 output (fwd||bwd concat)

// ---------------- f32x2 helpers ----------------
__device__ __forceinline__ void ffma2(unsigned long long& d, unsigned long long a, unsigned long long b) {
    asm("fma.rn.f32x2 %0, %1, %2, %0;" : "+l"(d) : "l"(a), "l"(b));
}
__device__ __forceinline__ float fold2(unsigned long long v) {
    float2 f; memcpy(&f, &v, 8); return f.x + f.y;
}
__device__ __forceinline__ unsigned long long pack2(float lo, float hi) {
    unsigned long long u;
    asm("mov.b64 %0, {%1, %2};" : "=l"(u) : "f"(lo), "f"(hi));
    return u;
}

// ---------------------------------------------------------------------------
// Input projection GEMM v2: xg[dir][r][j] = src[r][:] . W[dir][j][:] + bias[j]
// Tile 128(M) x 64(N) x 32(K-stage), 256 threads, 8m x 4n microtile,
// k-paired FFMA2, register double-buffered gmem prefetch.
// smem layout: [stage][kpair][row] float2  -> conflict-free LDS.128 frags.
// ---------------------------------------------------------------------------
__global__ __launch_bounds__(256, 1) void gemm_proj(
    const float* __restrict__ src, int K, int nst,
    const float* __restrict__ Wf, const float* __restrict__ bf,
    const float* __restrict__ Wb, const float* __restrict__ bb)
{
    const int dir = blockIdx.z;
    const float* __restrict__ W    = dir ? Wb : Wf;
    const float* __restrict__ bias = dir ? bb : bf;
    const int j0 = blockIdx.x * 64;
    const int r0 = blockIdx.y * 128;

    __shared__ __align__(16) float2 As2[2][16][128];   // 32 KB
    __shared__ __align__(16) float2 Bs2[2][16][64];    // 16 KB

    const int tid = threadIdx.x;

    // ---- loader mapping ----
    const int arow  = tid >> 1;        // 0..127
    const int ahalf = tid & 1;         // 0/1 : k half (16 floats)
    const int brow  = tid & 63;        // 0..63
    const int bq    = tid >> 6;        // 0..3 : k quarter (8 floats)
    const float* aptr = src + (size_t)(r0 + arow) * K + ahalf * 16;
    const float* bptr = W   + (size_t)(j0 + brow) * K + bq * 8;

    // ---- compute mapping ----
    const int wid  = tid >> 5;
    const int lane = tid & 31;
    const int mbase = (wid & 3) * 32 + (lane & 3) * 8;    // 8 consecutive rows
    const int nbase = (wid >> 2) * 32 + (lane >> 2) * 4;  // 4 consecutive cols

    unsigned long long acc[8][4];
    #pragma unroll
    for (int i = 0; i < 8; i++)
        #pragma unroll
        for (int u = 0; u < 4; u++) acc[i][u] = 0ull;

    float4 pa[4], pb[2];

    // stage 0 gmem load
    #pragma unroll
    for (int q = 0; q < 4; q++) pa[q] = *(const float4*)(aptr + q * 4);
    #pragma unroll
    for (int q = 0; q < 2; q++) pb[q] = *(const float4*)(bptr + q * 4);

    // stage 0 STS
    #pragma unroll
    for (int q = 0; q < 4; q++) {
        int kp = ahalf * 8 + q * 2;
        As2[0][kp    ][arow] = make_float2(pa[q].x, pa[q].y);
        As2[0][kp + 1][arow] = make_float2(pa[q].z, pa[q].w);
    }
    #pragma unroll
    for (int q = 0; q < 2; q++) {
        int kp = bq * 4 + q * 2;
        Bs2[0][kp    ][brow] = make_float2(pb[q].x, pb[q].y);
        Bs2[0][kp + 1][brow] = make_float2(pb[q].z, pb[q].w);
    }
    __syncthreads();

    int buf = 0;
    for (int s = 0; s < nst; ++s) {
        // prefetch next stage into registers (LDG hidden behind compute)
        if (s + 1 < nst) {
            const float* ap = aptr + (size_t)(s + 1) * 32;
            const float* bp = bptr + (size_t)(s + 1) * 32;
            #pragma unroll
            for (int q = 0; q < 4; q++) pa[q] = *(const float4*)(ap + q * 4);
            #pragma unroll
            for (int q = 0; q < 2; q++) pb[q] = *(const float4*)(bp + q * 4);
        }

        // compute current stage: 16 k-pairs
        #pragma unroll
        for (int kp = 0; kp < 16; ++kp) {
            ulonglong2 aA = *(const ulonglong2*)&As2[buf][kp][mbase    ];
            ulonglong2 aB = *(const ulonglong2*)&As2[buf][kp][mbase + 2];
            ulonglong2 aC = *(const ulonglong2*)&As2[buf][kp][mbase + 4];
            ulonglong2 aD = *(const ulonglong2*)&As2[buf][kp][mbase + 6];
            ulonglong2 bA = *(const ulonglong2*)&Bs2[buf][kp][nbase    ];
            ulonglong2 bB = *(const ulonglong2*)&Bs2[buf][kp][nbase + 2];
            unsigned long long av[8] = {aA.x, aA.y, aB.x, aB.y, aC.x, aC.y, aD.x, aD.y};
            unsigned long long bv[4] = {bA.x, bA.y, bB.x, bB.y};
            #pragma unroll
            for (int i = 0; i < 8; i++) {
                ffma2(acc[i][0], av[i], bv[0]);
                ffma2(acc[i][1], av[i], bv[1]);
                ffma2(acc[i][2], av[i], bv[2]);
                ffma2(acc[i][3], av[i], bv[3]);
            }
        }
        __syncthreads();

        if (s + 1 < nst) {
            const int nb = buf ^ 1;
            #pragma unroll
            for (int q = 0; q < 4; q++) {
                int kp = ahalf * 8 + q * 2;
                As2[nb][kp    ][arow] = make_float2(pa[q].x, pa[q].y);
                As2[nb][kp + 1][arow] = make_float2(pa[q].z, pa[q].w);
            }
            #pragma unroll
            for (int q = 0; q < 2; q++) {
                int kp = bq * 4 + q * 2;
                Bs2[nb][kp    ][brow] = make_float2(pb[q].x, pb[q].y);
                Bs2[nb][kp + 1][brow] = make_float2(pb[q].z, pb[q].w);
            }
            __syncthreads();
        }
        buf ^= 1;
    }

    // epilogue
    float4 bv4 = *(const float4*)&bias[j0 + nbase];
    #pragma unroll
    for (int i = 0; i < 8; i++) {
        float4 o;
        o.x = fold2(acc[i][0]) + bv4.x;
        o.y = fold2(acc[i][1]) + bv4.y;
        o.z = fold2(acc[i][2]) + bv4.z;
        o.w = fold2(acc[i][3]) + bv4.w;
        *(float4*)(g_xg + ((size_t)dir * (BATCH * TT) + r0 + mbase + i) * NGATE + j0 + nbase) = o;
    }
}

// ---------------------------------------------------------------------------
// Recurrence (unchanged from R4 — passing): W_hh in registers, f32x2 math,
// vectorized DSMEM h exchange, 8-CTA clusters.
// ---------------------------------------------------------------------------
__device__ __forceinline__ float sigmoidf_(float x) { return 1.0f / (1.0f + __expf(-x)); }

__global__ __launch_bounds__(256, 1) __cluster_dims__(8, 1, 1)
void lstm_rec(const float* __restrict__ whhF, const float* __restrict__ whhB,
              float* __restrict__ out)
{
    __shared__ __align__(16) float h_s[2 * 1024];   // [2 buf][4 batch][256]
    __shared__ float g_s [512];
    __shared__ float rsum[512];
    __shared__ __align__(16) float hstage[128];

    const int tid   = threadIdx.x;
    const int j     = tid & 127;
    const int kh    = tid >> 7;
    const int brank = blockIdx.x & 7;
    const int cid   = blockIdx.x >> 3;
    const int dir   = cid >> 3;
    const int bg    = cid & 7;
    const float* __restrict__ whh = dir ? whhB : whhF;

    const int gate = j >> 5;
    const int kl   = j & 31;
    const int grow = (gate << 8) + (brank << 5) + kl;

    unsigned long long Wreg[64];
    {
        const float* wrow = whh + (size_t)grow * HDIM + (kh << 7);
        #pragma unroll
        for (int q = 0; q < 64; ++q) {
            float2 w = *(const float2*)(wrow + 2 * q);
            memcpy(&Wreg[q], &w, 8);
        }
    }

    for (int idx = tid; idx < 2048; idx += 256) h_s[idx] = 0.f;
    __syncthreads();
    asm volatile("barrier.cluster.arrive.aligned;\n\tbarrier.cluster.wait.aligned;" ::: "memory");

    uint32_t mypeer;
    {
        uint32_t hbase;
        asm volatile("{ .reg .u64 t; cvta.to.shared.u64 t, %1; cvt.u32.u64 %0, t; }"
                     : "=r"(hbase) : "l"((const float*)h_s));
        uint32_t rk = (uint32_t)(tid >> 5);
        asm volatile("mapa.shared::cluster.u32 %0, %1, %2;" : "=r"(mypeer) : "r"(hbase), "r"(rk));
    }
    const int i5 = tid & 31;
    const uint32_t push_off = ((uint32_t)(i5 >> 3) << 10) + ((uint32_t)brank << 7) + ((uint32_t)(i5 & 7) << 4);

    const float* xgb = g_xg + (((size_t)dir * BATCH + bg * 4) * TT) * NGATE;

    float c_state = 0.f;
    int t = dir ? (TT - 1) : 0;
    const int tstep = dir ? -1 : 1;

    float x0 = 0.f, x1 = 0.f, x2 = 0.f, x3 = 0.f;
    if (kh == 0) {
        x0 = xgb[((size_t)0 * TT + t) * NGATE + grow];
        x1 = xgb[((size_t)1 * TT + t) * NGATE + grow];
        x2 = xgb[((size_t)2 * TT + t) * NGATE + grow];
        x3 = xgb[((size_t)3 * TT + t) * NGATE + grow];
    }

    int buf = 0;
    for (int it = 0; it < TT; ++it) {
        unsigned long long acc0, acc1, acc2, acc3;
        if (kh == 0) {
            acc0 = pack2(x0, 0.f); acc1 = pack2(x1, 0.f);
            acc2 = pack2(x2, 0.f); acc3 = pack2(x3, 0.f);
        } else {
            acc0 = acc1 = acc2 = acc3 = 0ull;
        }

        const ulonglong2* hptr = reinterpret_cast<const ulonglong2*>(h_s + (buf << 10) + (kh << 7));
        #pragma unroll
        for (int q = 0; q < 32; ++q) {
            ulonglong2 ha = hptr[q];
            ulonglong2 hb = hptr[q + 64];
            ulonglong2 hc = hptr[q + 128];
            ulonglong2 hd = hptr[q + 192];
            unsigned long long w0 = Wreg[2 * q], w1 = Wreg[2 * q + 1];
            ffma2(acc0, w0, ha.x); ffma2(acc1, w0, hb.x);
            ffma2(acc2, w0, hc.x); ffma2(acc3, w0, hd.x);
            ffma2(acc0, w1, ha.y); ffma2(acc1, w1, hb.y);
            ffma2(acc2, w1, hc.y); ffma2(acc3, w1, hd.y);
        }

        float s0 = fold2(acc0), s1 = fold2(acc1), s2 = fold2(acc2), s3 = fold2(acc3);
        if (kh == 0) {
            g_s[      j] = s0; g_s[128 + j] = s1; g_s[256 + j] = s2; g_s[384 + j] = s3;
        } else {
            rsum[      j] = s0; rsum[128 + j] = s1; rsum[256 + j] = s2; rsum[384 + j] = s3;
        }
        __syncthreads();

        float hval = 0.f;
        if (tid < 128) {
            const int bb   = tid >> 5;
            const int kloc = tid & 31;
            const int base = bb * 128 + kloc;
            float gi = g_s[base     ] + rsum[base     ];
            float gf = g_s[base + 32] + rsum[base + 32];
            float gg = g_s[base + 64] + rsum[base + 64];
            float go = g_s[base + 96] + rsum[base + 96];
            float i_ = sigmoidf_(gi);
            float f_ = sigmoidf_(gf);
            float g_ = tanhf(gg);
            float o_ = sigmoidf_(go);
            c_state = f_ * c_state + i_ * g_;
            hval = o_ * tanhf(c_state);
            hstage[tid] = hval;
        }
        __syncthreads();

        {
            const float4 v = *(const float4*)&hstage[i5 << 2];
            uint32_t addr = mypeer + ((uint32_t)(buf ^ 1) << 12) + push_off;
            asm volatile("st.shared::cluster.v4.f32 [%0], {%1, %2, %3, %4};"
                         :: "r"(addr), "f"(v.x), "f"(v.y), "f"(v.z), "f"(v.w) : "memory");
        }
        asm volatile("barrier.cluster.arrive.aligned;" ::: "memory");

        if (tid < 128) {
            const int bb   = tid >> 5;
            const int kloc = tid & 31;
            out[(((size_t)(bg * 4 + bb)) * TT + t) * OUTW + (dir << 8) + (brank << 5) + kloc] = hval;
        }
        if (kh == 0 && it + 1 < TT) {
            const int tnx = t + tstep;
            x0 = xgb[((size_t)0 * TT + tnx) * NGATE + grow];
            x1 = xgb[((size_t)1 * TT + tnx) * NGATE + grow];
            x2 = xgb[((size_t)2 * TT + tnx) * NGATE + grow];
            x3 = xgb[((size_t)3 * TT + tnx) * NGATE + grow];
        }

        asm volatile("barrier.cluster.wait.aligned;" ::: "memory");
        buf ^= 1;
        t += tstep;
    }
}

// ---------------------------------------------------------------------------
extern "C" void kernel_launch(void* const* d_in, const int* in_sizes, int n_in,
                              void* d_out, int out_size)
{
    const float* x         = (const float*)d_in[0];
    const float* w_ih_l0f  = (const float*)d_in[1];
    const float* w_hh_l0f  = (const float*)d_in[2];
    const float* b_l0f     = (const float*)d_in[3];
    const float* w_ih_l0b  = (const float*)d_in[4];
    const float* w_hh_l0b  = (const float*)d_in[5];
    const float* b_l0b     = (const float*)d_in[6];
    const float* w_ih_l1f  = (const float*)d_in[7];
    const float* w_hh_l1f  = (const float*)d_in[8];
    const float* b_l1f     = (const float*)d_in[9];
    const float* w_ih_l1b  = (const float*)d_in[10];
    const float* w_hh_l1b  = (const float*)d_in[11];
    const float* b_l1b     = (const float*)d_in[12];
    float* out = (float*)d_out;

    float* h1 = nullptr;
    cudaGetSymbolAddress((void**)&h1, g_h1);

    dim3 ggrid(16, 128, 2);   // N/64, M/128, dirs

    // Layer 0 (K=256, 8 stages)
    gemm_proj<<<ggrid, 256>>>(x, 256, 8, w_ih_l0f, b_l0f, w_ih_l0b, b_l0b);
    lstm_rec<<<128, 256>>>(w_hh_l0f, w_hh_l0b, h1);

    // Layer 1 (K=512, 16 stages)
    gemm_proj<<<ggrid, 256>>>(h1, 512, 16, w_ih_l1f, b_l1f, w_ih_l1b, b_l1b);
    lstm_rec<<<128, 256>>>(w_hh_l1f, w_hh_l1b, out);
}